// round 3
// baseline (speedup 1.0000x reference)
#include <cuda_runtime.h>
#include <cstddef>

#define TSTEPS 1024
#define BATCH  64
#define DIN    256
#define DHID   256
#define NC     1024
#define M_TOTAL (TSTEPS * BATCH)

#define CLUSTER 8
#define NCTA    128
#define RTHR    512

// packed column: pc = part*128 + gate*32 + u, where j = part*32 + u, gate in {f,i,g,o}

__device__ float g_xp[(size_t)M_TOTAL * NC];   // x-proj + bias, [t*B + b][pc]
__device__ float g_Wxp[DIN * NC];              // packed Wx [k][pc]
__device__ float g_Whp[DHID * NC];             // packed Wh [part][kc][i][c]
__device__ float g_bp[NC];                     // packed bias [pc]

// ------------------------- pack weights -------------------------
__global__ void pack_kernel(const float* __restrict__ Wf, const float* __restrict__ bf,
                            const float* __restrict__ Wi, const float* __restrict__ bi,
                            const float* __restrict__ Wg, const float* __restrict__ bg,
                            const float* __restrict__ Wo, const float* __restrict__ bo)
{
    int idx = blockIdx.x * blockDim.x + threadIdx.x;
    if (idx >= DIN * NC) return;
    int k    = idx >> 10;
    int pc   = idx & (NC - 1);
    int part = pc >> 7;
    int gate = (pc >> 5) & 3;
    int u    = pc & 31;
    int j    = part * 32 + u;
    const float* W = (gate == 0) ? Wf : (gate == 1) ? Wi : (gate == 2) ? Wg : Wo;
    const float* b = (gate == 0) ? bf : (gate == 1) ? bi : (gate == 2) ? bg : bo;
    g_Wxp[idx] = W[(size_t)k * DHID + j];
    int kc = k >> 6, i = k & 63;
    g_Whp[(size_t)(((part * 4 + kc) * 64) + i) * 128 + (pc & 127)] =
        W[(size_t)(DIN + k) * DHID + j];
    if (k == 0) g_bp[pc] = b[j];
}

// ------------------------- xproj: g_xp = X @ g_Wxp + g_bp -------------------------
// M=65536, N=1024, K=256. 128x128 tile, BK=8, 256 threads, 8x8 micro-tile via fma.rn.f32x2.
// A stored duplicated in smem so (a,a) u64 operands come straight from LDS.128.
__global__ __launch_bounds__(256, 2) void xproj_kernel(const float* __restrict__ X)
{
    __shared__ __align__(16) unsigned long long As2[8][128];  // [k][m] duplicated pairs (8 KB)
    __shared__ __align__(16) float Bs[8][128];                // [k][n] (4 KB)

    const int tid = threadIdx.x;
    const int m0  = blockIdx.y * 128;
    const int n0  = blockIdx.x * 128;
    const int ty  = tid >> 4;     // 0..15 -> 8 m rows
    const int tx  = tid & 15;     // 0..15 -> 8 n cols

    // staging thread roles
    const int pm  = tid >> 1;     // A: row 0..127
    const int pkq = tid & 1;      // A: k-quad 0..1
    const int pk  = tid >> 5;     // B: k 0..7
    const int pnq = tid & 31;     // B: n-quad 0..31

    unsigned long long acc2[8][4];
    #pragma unroll
    for (int i = 0; i < 8; i++)
        #pragma unroll
        for (int jj = 0; jj < 4; jj++) acc2[i][jj] = 0ull;

    float4 av = *(const float4*)&X[(size_t)(m0 + pm) * DIN + pkq * 4];
    float4 bv = *(const float4*)&g_Wxp[(size_t)pk * NC + n0 + pnq * 4];

    for (int k0 = 0; k0 < DIN; k0 += 8) {
        __syncthreads();
        // stage A duplicated
        {
            unsigned long long d;
            asm("mov.b64 %0, {%1, %1};" : "=l"(d) : "f"(av.x)); As2[pkq * 4 + 0][pm] = d;
            asm("mov.b64 %0, {%1, %1};" : "=l"(d) : "f"(av.y)); As2[pkq * 4 + 1][pm] = d;
            asm("mov.b64 %0, {%1, %1};" : "=l"(d) : "f"(av.z)); As2[pkq * 4 + 2][pm] = d;
            asm("mov.b64 %0, {%1, %1};" : "=l"(d) : "f"(av.w)); As2[pkq * 4 + 3][pm] = d;
        }
        *(float4*)&Bs[pk][pnq * 4] = bv;
        __syncthreads();

        if (k0 + 8 < DIN) {
            av = *(const float4*)&X[(size_t)(m0 + pm) * DIN + (k0 + 8) + pkq * 4];
            bv = *(const float4*)&g_Wxp[(size_t)(k0 + 8 + pk) * NC + n0 + pnq * 4];
        }

        #pragma unroll
        for (int k = 0; k < 8; k++) {
            unsigned long long a[8];
            #pragma unroll
            for (int q = 0; q < 4; q++) {
                ulonglong2 t2 = *(const ulonglong2*)&As2[k][ty * 8 + q * 2];
                a[q * 2 + 0] = t2.x;
                a[q * 2 + 1] = t2.y;
            }
            ulonglong2 bb0 = *(const ulonglong2*)&Bs[k][tx * 8];
            ulonglong2 bb1 = *(const ulonglong2*)&Bs[k][tx * 8 + 4];
            unsigned long long bp[4] = { bb0.x, bb0.y, bb1.x, bb1.y };
            #pragma unroll
            for (int i = 0; i < 8; i++)
                #pragma unroll
                for (int jj = 0; jj < 4; jj++)
                    asm("fma.rn.f32x2 %0, %1, %2, %0;"
                        : "+l"(acc2[i][jj]) : "l"(a[i]), "l"(bp[jj]));
        }
    }

    float4 bias0 = *(const float4*)&g_bp[n0 + tx * 8];
    float4 bias1 = *(const float4*)&g_bp[n0 + tx * 8 + 4];
    #pragma unroll
    for (int i = 0; i < 8; i++) {
        float r[8];
        #pragma unroll
        for (int jj = 0; jj < 4; jj++)
            asm("mov.b64 {%0, %1}, %2;" : "=f"(r[jj * 2]), "=f"(r[jj * 2 + 1]) : "l"(acc2[i][jj]));
        float4 o0 = make_float4(r[0] + bias0.x, r[1] + bias0.y, r[2] + bias0.z, r[3] + bias0.w);
        float4 o1 = make_float4(r[4] + bias1.x, r[5] + bias1.y, r[6] + bias1.z, r[7] + bias1.w);
        float* dst = &g_xp[(size_t)(m0 + ty * 8 + i) * NC + n0 + tx * 8];
        *(float4*)dst       = o0;
        *(float4*)(dst + 4) = o1;
    }
}

// ------------------------- recurrent kernel: 16 clusters of 8 CTAs -------------------------
__global__ void __cluster_dims__(CLUSTER, 1, 1) __launch_bounds__(RTHR, 1)
recur_kernel(float* __restrict__ out, int out_size)
{
    __shared__ __align__(16) float hbuf[2][DHID * 4];   // [buf][k*4 + b]   (8 KB)
    __shared__ __align__(16) float pbuf[4][4][128];     // [kc][b][c]       (8 KB)
    __shared__ float act[4][128];                       // [gate][b*32+u]   (2 KB)

    const int tid  = threadIdx.x;
    const int part = blockIdx.x & (CLUSTER - 1);
    const int grp  = blockIdx.x >> 3;
    const int kc   = tid >> 7;        // 0..3 : k-chunk (stage1) == gate (stage2a)
    const int c    = tid & 127;       // 0..127 packed column (stage1)
    const int ab   = (tid >> 5) & 3;  // batch (stage2a)
    const int au   = tid & 31;        // unit  (stage2a)

    // preload Wh slice into registers (coalesced: stride 128 over 64 rows)
    float w[64];
    {
        const float* src = &g_Whp[(size_t)((part * 4 + kc) * 64) * 128 + c];
        #pragma unroll
        for (int i = 0; i < 64; i++) w[i] = src[(size_t)i * 128];
    }

    for (int i = tid; i < 2 * DHID * 4; i += RTHR) ((float*)hbuf)[i] = 0.0f;

    // stage2b identity (threads 0..127)
    const int cb = tid >> 5;
    const int cu = tid & 31;
    const int bg = grp * 4 + cb;
    const int j  = part * 32 + cu;
    float cstate = 0.0f;

    unsigned hbuf_base;
    asm("{ .reg .u64 t; cvta.to.shared.u64 t, %1; cvt.u32.u64 %0, t; }"
        : "=r"(hbuf_base) : "l"((void*)hbuf));

    __syncthreads();

    const size_t HT_OFF = (size_t)TSTEPS * BATCH * DHID;

    for (int t = 0; t < TSTEPS; t++) {
        const int p = t & 1;

        // prefetch this step's x-projection (1 scalar per thread, coalesced; overlaps stage1)
        float xpv = g_xp[((size_t)t * BATCH + grp * 4 + ab) * NC + part * 128 + kc * 32 + au];

        // ---- stage 1: partial dots over this thread's 64-k chunk, 4 batches via fma2 ----
        {
            unsigned long long acc01 = 0ull, acc23 = 0ull;
            const float* hrow = &hbuf[p][kc * 256];
            #pragma unroll
            for (int i = 0; i < 64; i++) {
                ulonglong2 hh = *(const ulonglong2*)&hrow[i * 4];
                unsigned long long ww;
                asm("mov.b64 %0, {%1, %1};" : "=l"(ww) : "f"(w[i]));
                asm("fma.rn.f32x2 %0, %1, %2, %0;" : "+l"(acc01) : "l"(ww), "l"(hh.x));
                asm("fma.rn.f32x2 %0, %1, %2, %0;" : "+l"(acc23) : "l"(ww), "l"(hh.y));
            }
            float a0, a1, a2, a3;
            asm("mov.b64 {%0, %1}, %2;" : "=f"(a0), "=f"(a1) : "l"(acc01));
            asm("mov.b64 {%0, %1}, %2;" : "=f"(a2), "=f"(a3) : "l"(acc23));
            pbuf[kc][0][c] = a0;
            pbuf[kc][1][c] = a1;
            pbuf[kc][2][c] = a2;
            pbuf[kc][3][c] = a3;
        }
        __syncthreads();

        // ---- stage 2a: gate pre-activation + nonlinearity, all 512 threads (1 MUFU each) ----
        {
            const int cc = kc * 32 + au;   // packed column for (gate=kc, u=au)
            float s = pbuf[0][ab][cc] + pbuf[1][ab][cc]
                    + pbuf[2][ab][cc] + pbuf[3][ab][cc] + xpv;
            float r;
            if (kc == 2) {                          // g gate: tanh
                asm("tanh.approx.f32 %0, %1;" : "=f"(r) : "f"(s));
            } else {                                // f,i,o: sigmoid via tanh
                float th;
                asm("tanh.approx.f32 %0, %1;" : "=f"(th) : "f"(0.5f * s));
                r = 0.5f * th + 0.5f;
            }
            act[kc][ab * 32 + au] = r;
        }
        __syncthreads();

        // ---- stage 2b: cell/hidden update + outputs + DSMEM broadcast (threads 0..127) ----
        if (tid < 128) {
            float fv = act[0][tid];
            float iv = act[1][tid];
            float gv = act[2][tid];
            float ov = act[3][tid];
            cstate = fv * cstate + iv * gv;
            float ct;
            asm("tanh.approx.f32 %0, %1;" : "=f"(ct) : "f"(cstate));
            float h = ov * ct;

            out[(size_t)t * (BATCH * DHID) + (size_t)bg * DHID + j] = h;
            if (t == TSTEPS - 1) {
                if ((size_t)out_size >= HT_OFF + (size_t)BATCH * DHID)
                    out[HT_OFF + (size_t)bg * DHID + j] = h;
                if ((size_t)out_size >= HT_OFF + 2 * (size_t)BATCH * DHID)
                    out[HT_OFF + (size_t)BATCH * DHID + (size_t)bg * DHID + j] = cstate;
            }

            unsigned dst = hbuf_base + (unsigned)(((1 - p) * DHID * 4 + j * 4 + cb) * 4);
            #pragma unroll
            for (int r = 0; r < CLUSTER; r++) {
                unsigned rem;
                asm("mapa.shared::cluster.u32 %0, %1, %2;" : "=r"(rem) : "r"(dst), "r"(r));
                asm volatile("st.shared::cluster.f32 [%0], %1;" :: "r"(rem), "f"(h) : "memory");
            }
        }

        asm volatile("barrier.cluster.arrive.aligned;" ::: "memory");
        asm volatile("barrier.cluster.wait.aligned;" ::: "memory");
    }
}

// ------------------------- launch -------------------------
extern "C" void kernel_launch(void* const* d_in, const int* in_sizes, int n_in,
                              void* d_out, int out_size)
{
    const float* X  = (const float*)d_in[0];
    const float* Wf = (const float*)d_in[1];
    const float* bf = (const float*)d_in[2];
    const float* Wi = (const float*)d_in[3];
    const float* bi = (const float*)d_in[4];
    const float* Wg = (const float*)d_in[5];
    const float* bg = (const float*)d_in[6];
    const float* Wo = (const float*)d_in[7];
    const float* bo = (const float*)d_in[8];
    float* out = (float*)d_out;

    pack_kernel<<<(DIN * NC + 255) / 256, 256>>>(Wf, bf, Wi, bi, Wg, bg, Wo, bo);

    dim3 ggrid(NC / 128, M_TOTAL / 128);
    xproj_kernel<<<ggrid, 256>>>(X);

    recur_kernel<<<NCTA, RTHR>>>(out, out_size);
}

// round 7
// speedup vs baseline: 1.1832x; 1.1832x over previous
#include <cuda_runtime.h>
#include <cuda_bf16.h>
#include <cstddef>
#include <cstdint>

#define TSTEPS 1024
#define BATCH  64
#define DIN    256
#define DHID   256
#define NC     1024
#define M_TOTAL (TSTEPS * BATCH)
#define KTOT   768            // split-bf16 virtual K: [Xhi|Xhi|Xlo] x [Whi;Wlo;Whi]

#define CLUSTER 8
#define NCTA    128
#define RTHR    512

// packed column: pc = part*128 + u*4 + gate, j = part*32 + u, gate in {f,i,g,o}

__device__ float         g_xp[(size_t)M_TOTAL * NC];     // x-proj + bias [m][pc]
__device__ __nv_bfloat16 g_Ax[(size_t)M_TOTAL * KTOT];   // split-bf16 A' [m][k']
__device__ __nv_bfloat16 g_Bx[(size_t)NC * KTOT];        // split-bf16 B' [pc][k']
__device__ float         g_Whp[DHID * NC];               // fp32 Wh for recur
__device__ float         g_bp[NC];

// ============================ helpers ============================
__device__ __forceinline__ uint32_t smem_u32(const void* p) {
    uint32_t a;
    asm("{ .reg .u64 t; cvta.to.shared.u64 t, %1; cvt.u32.u64 %0, t; }" : "=r"(a) : "l"(p));
    return a;
}
// SW128(row*128 + d) = row*128 + (d ^ ((row<<4)&0x70))  for d < 128
#define SW128(off) ((off) ^ (((off) >> 3) & 0x70))

__device__ __forceinline__ void ldsm4(uint32_t* r, uint32_t addr) {
    asm volatile("ldmatrix.sync.aligned.m8n8.x4.shared.b16 {%0,%1,%2,%3}, [%4];"
                 : "=r"(r[0]), "=r"(r[1]), "=r"(r[2]), "=r"(r[3]) : "r"(addr));
}
__device__ __forceinline__ void mma16816(float* c, const uint32_t* a, uint32_t b0, uint32_t b1) {
    asm volatile("mma.sync.aligned.m16n8k16.row.col.f32.bf16.bf16.f32 "
                 "{%0,%1,%2,%3}, {%4,%5,%6,%7}, {%8,%9}, {%0,%1,%2,%3};"
                 : "+f"(c[0]), "+f"(c[1]), "+f"(c[2]), "+f"(c[3])
                 : "r"(a[0]), "r"(a[1]), "r"(a[2]), "r"(a[3]), "r"(b0), "r"(b1));
}

// ============================ pack kernels ============================
__global__ void packB_kernel(const float* __restrict__ Wf, const float* __restrict__ bf,
                             const float* __restrict__ Wi, const float* __restrict__ bi,
                             const float* __restrict__ Wg, const float* __restrict__ bg,
                             const float* __restrict__ Wo, const float* __restrict__ bo)
{
    int idx = blockIdx.x * blockDim.x + threadIdx.x;
    if (idx >= DIN * NC) return;
    int k    = idx >> 10;
    int pc   = idx & (NC - 1);
    int part = pc >> 7;
    int c    = pc & 127;
    int u    = c >> 2;
    int gate = c & 3;
    int j    = part * 32 + u;
    const float* W = (gate == 0) ? Wf : (gate == 1) ? Wi : (gate == 2) ? Wg : Wo;
    const float* b = (gate == 0) ? bf : (gate == 1) ? bi : (gate == 2) ? bg : bo;

    float wx = W[(size_t)k * DHID + j];
    __nv_bfloat16 hi = __float2bfloat16_rn(wx);
    float lo = wx - __bfloat162float(hi);
    g_Bx[(size_t)pc * KTOT + k]       = hi;                        // pairs with Xhi
    g_Bx[(size_t)pc * KTOT + 256 + k] = __float2bfloat16_rn(lo);   // pairs with Xhi
    g_Bx[(size_t)pc * KTOT + 512 + k] = hi;                        // pairs with Xlo

    float wh = W[(size_t)(DIN + k) * DHID + j];
    int kc = k >> 6, i = k & 63;
    g_Whp[(size_t)(((part * 4 + kc) * 64) + i) * 128 + c] = wh;
    if (k == 0) g_bp[pc] = b[j];
}

__global__ void packA_kernel(const float* __restrict__ X)
{
    int idx = blockIdx.x * blockDim.x + threadIdx.x;
    if (idx >= M_TOTAL * (DIN / 4)) return;
    int m  = idx >> 6;
    int kq = idx & 63;
    float4 v = *(const float4*)&X[(size_t)m * DIN + kq * 4];
    __nv_bfloat162 h0 = __floats2bfloat162_rn(v.x, v.y);
    __nv_bfloat162 h1 = __floats2bfloat162_rn(v.z, v.w);
    float lx = v.x - __bfloat162float(h0.x);
    float ly = v.y - __bfloat162float(h0.y);
    float lz = v.z - __bfloat162float(h1.x);
    float lw = v.w - __bfloat162float(h1.y);
    __nv_bfloat162 l0 = __floats2bfloat162_rn(lx, ly);
    __nv_bfloat162 l1 = __floats2bfloat162_rn(lz, lw);
    size_t base = (size_t)m * KTOT + kq * 4;
    *(__nv_bfloat162*)&g_Ax[base]       = h0;
    *(__nv_bfloat162*)&g_Ax[base + 2]   = h1;
    *(__nv_bfloat162*)&g_Ax[base + 256] = h0;
    *(__nv_bfloat162*)&g_Ax[base + 258] = h1;
    *(__nv_bfloat162*)&g_Ax[base + 512] = l0;
    *(__nv_bfloat162*)&g_Ax[base + 514] = l1;
}

// ============================ xproj GEMM: mma.sync bf16 ============================
// per CTA: M=128, N=128, K=768 in 12 chunks of 64. grid (8, 512). 256 thr = 8 warps (2m x 4n).
// smem: sA/sB 128 rows x 64 bf16 (128B rows, SW128 swizzle), 16 KB each.
// Resubmission of R6 (unverified due to container infra failure; code audit clean).
#define XT 256
#define BK 64
#define NCHUNK (KTOT / BK)

__global__ __launch_bounds__(XT) void xproj_mma()
{
    __shared__ __align__(128) __nv_bfloat16 sAbuf[128 * 64];
    __shared__ __align__(128) __nv_bfloat16 sBbuf[128 * 64];

    const int tid    = threadIdx.x;
    const int wid    = tid >> 5;
    const int lane   = tid & 31;
    const int warp_m = wid >> 2;        // 0..1
    const int warp_n = wid & 3;         // 0..3
    const int n0     = blockIdx.x * 128;
    const int m0     = blockIdx.y * 128;

    const uint32_t sA32 = smem_u32(sAbuf);
    const uint32_t sB32 = smem_u32(sBbuf);
    char* sAp = (char*)sAbuf;
    char* sBp = (char*)sBbuf;

    // ldmatrix per-thread geometry
    const int g  = lane >> 3;           // 0..3 (8-thread group)
    const int lr = lane & 7;
    // A x4: g0: rows 0-7 @+0 | g1: rows 8-15 @+0 | g2: rows 0-7 @+16B | g3: rows 8-15 @+16B
    const int rA   = warp_m * 64 + (g & 1) * 8 + lr;   // + mt*16
    const int hbA  = (g >> 1) * 16;
    // B x4: g0: n0-7 @+0 | g1: n0-7 @+16B | g2: n8-15 @+0 | g3: n8-15 @+16B  (covers 2 n-tiles)
    const int rB   = warp_n * 32 + (g >> 1) * 8 + lr;  // + h*16
    const int hbB  = (g & 1) * 16;

    float acc[4][4][4];
    #pragma unroll
    for (int i = 0; i < 4; i++)
        #pragma unroll
        for (int jj = 0; jj < 4; jj++)
            #pragma unroll
            for (int q = 0; q < 4; q++) acc[i][jj][q] = 0.0f;

    // register prefetch of chunk 0 (4 uint4 per thread per tile)
    uint4 rAv[4], rBv[4];
    #pragma unroll
    for (int i = 0; i < 4; i++) {
        int idx = tid + i * 256, row = idx >> 3, q = idx & 7;
        rAv[i] = *(const uint4*)&g_Ax[(size_t)(m0 + row) * KTOT + q * 8];
        rBv[i] = *(const uint4*)&g_Bx[(size_t)(n0 + row) * KTOT + q * 8];
    }

    for (int c = 0; c < NCHUNK; c++) {
        #pragma unroll
        for (int i = 0; i < 4; i++) {
            int idx = tid + i * 256, row = idx >> 3, q = idx & 7;
            *(uint4*)(sAp + SW128(row * 128 + q * 16)) = rAv[i];
            *(uint4*)(sBp + SW128(row * 128 + q * 16)) = rBv[i];
        }
        __syncthreads();

        if (c + 1 < NCHUNK) {
            #pragma unroll
            for (int i = 0; i < 4; i++) {
                int idx = tid + i * 256, row = idx >> 3, q = idx & 7;
                rAv[i] = *(const uint4*)&g_Ax[(size_t)(m0 + row) * KTOT + (c + 1) * BK + q * 8];
                rBv[i] = *(const uint4*)&g_Bx[(size_t)(n0 + row) * KTOT + (c + 1) * BK + q * 8];
            }
        }

        #pragma unroll
        for (int kk = 0; kk < 4; kk++) {
            uint32_t a[4][4], b[2][4];
            #pragma unroll
            for (int mt = 0; mt < 4; mt++) {
                int row = rA + mt * 16;
                ldsm4(a[mt], sA32 + row * 128 + ((kk * 32 + hbA) ^ ((row << 4) & 0x70)));
            }
            #pragma unroll
            for (int h = 0; h < 2; h++) {
                int row = rB + h * 16;
                ldsm4(b[h], sB32 + row * 128 + ((kk * 32 + hbB) ^ ((row << 4) & 0x70)));
            }
            #pragma unroll
            for (int mt = 0; mt < 4; mt++)
                #pragma unroll
                for (int nt = 0; nt < 4; nt++)
                    mma16816(acc[mt][nt], a[mt], b[nt >> 1][(nt & 1) * 2], b[nt >> 1][(nt & 1) * 2 + 1]);
        }
        __syncthreads();
    }

    // epilogue: fragment direct stores + bias
    const int er = lane >> 2;            // row within tile
    const int ec = (lane & 3) * 2;       // col pair within tile
    #pragma unroll
    for (int mt = 0; mt < 4; mt++) {
        int m = m0 + warp_m * 64 + mt * 16 + er;
        #pragma unroll
        for (int nt = 0; nt < 4; nt++) {
            int n = n0 + warp_n * 32 + nt * 8 + ec;
            float2 bias = *(const float2*)&g_bp[n];
            float2 o0 = make_float2(acc[mt][nt][0] + bias.x, acc[mt][nt][1] + bias.y);
            float2 o1 = make_float2(acc[mt][nt][2] + bias.x, acc[mt][nt][3] + bias.y);
            *(float2*)&g_xp[(size_t)m * NC + n]       = o0;
            *(float2*)&g_xp[(size_t)(m + 8) * NC + n] = o1;
        }
    }
}

// ============================ recurrent kernel (R2, proven) ============================
__global__ void __cluster_dims__(CLUSTER, 1, 1) __launch_bounds__(RTHR, 1)
recur_kernel(float* __restrict__ out, int out_size)
{
    __shared__ __align__(16) float hbuf[2][DHID * 4];
    __shared__ __align__(16) float pbuf[4][4][128];

    const int tid  = threadIdx.x;
    const int part = blockIdx.x & (CLUSTER - 1);
    const int grp  = blockIdx.x >> 3;
    const int kc   = tid >> 7;
    const int c    = tid & 127;

    float w[64];
    {
        const float* src = &g_Whp[(size_t)((part * 4 + kc) * 64) * 128 + c];
        #pragma unroll
        for (int i = 0; i < 64; i++) w[i] = src[(size_t)i * 128];
    }

    for (int i = tid; i < 2 * DHID * 4; i += RTHR) ((float*)hbuf)[i] = 0.0f;

    const int cb = tid >> 5;
    const int cu = tid & 31;
    const int bg = grp * 4 + cb;
    const int j  = part * 32 + cu;
    float cstate = 0.0f;

    unsigned hbuf_base;
    asm("{ .reg .u64 t; cvta.to.shared.u64 t, %1; cvt.u32.u64 %0, t; }"
        : "=r"(hbuf_base) : "l"((void*)hbuf));

    __syncthreads();

    const size_t HT_OFF = (size_t)TSTEPS * BATCH * DHID;

    for (int t = 0; t < TSTEPS; t++) {
        const int p = t & 1;

        float4 xp4;
        if (tid < 128)
            xp4 = *(const float4*)&g_xp[((size_t)t * BATCH + bg) * NC + part * 128 + cu * 4];

        {
            unsigned long long acc01 = 0ull, acc23 = 0ull;
            const float* hrow = &hbuf[p][kc * 256];
            #pragma unroll
            for (int i = 0; i < 64; i++) {
                ulonglong2 hh = *(const ulonglong2*)&hrow[i * 4];
                unsigned long long ww;
                asm("mov.b64 %0, {%1, %1};" : "=l"(ww) : "f"(w[i]));
                asm("fma.rn.f32x2 %0, %1, %2, %0;" : "+l"(acc01) : "l"(ww), "l"(hh.x));
                asm("fma.rn.f32x2 %0, %1, %2, %0;" : "+l"(acc23) : "l"(ww), "l"(hh.y));
            }
            float a0, a1, a2, a3;
            asm("mov.b64 {%0, %1}, %2;" : "=f"(a0), "=f"(a1) : "l"(acc01));
            asm("mov.b64 {%0, %1}, %2;" : "=f"(a2), "=f"(a3) : "l"(acc23));
            pbuf[kc][0][c] = a0;
            pbuf[kc][1][c] = a1;
            pbuf[kc][2][c] = a2;
            pbuf[kc][3][c] = a3;
        }
        __syncthreads();

        if (tid < 128) {
            float4 s = make_float4(0.f, 0.f, 0.f, 0.f);
            #pragma unroll
            for (int q = 0; q < 4; q++) {
                float4 p4 = *(const float4*)&pbuf[q][cb][cu * 4];
                s.x += p4.x; s.y += p4.y; s.z += p4.z; s.w += p4.w;
            }
            float fv = s.x + xp4.x;
            float iv = s.y + xp4.y;
            float gv = s.z + xp4.z;
            float ov = s.w + xp4.w;
            fv = 1.0f / (1.0f + __expf(-fv));
            iv = 1.0f / (1.0f + __expf(-iv));
            ov = 1.0f / (1.0f + __expf(-ov));
            float gt, ht;
            asm("tanh.approx.f32 %0, %1;" : "=f"(gt) : "f"(gv));
            cstate = fv * cstate + iv * gt;
            asm("tanh.approx.f32 %0, %1;" : "=f"(ht) : "f"(cstate));
            float h = ov * ht;

            out[(size_t)t * (BATCH * DHID) + (size_t)bg * DHID + j] = h;
            if (t == TSTEPS - 1) {
                if ((size_t)out_size >= HT_OFF + (size_t)BATCH * DHID)
                    out[HT_OFF + (size_t)bg * DHID + j] = h;
                if ((size_t)out_size >= HT_OFF + 2 * (size_t)BATCH * DHID)
                    out[HT_OFF + (size_t)BATCH * DHID + (size_t)bg * DHID + j] = cstate;
            }

            unsigned dst = hbuf_base + (unsigned)(((1 - p) * DHID * 4 + j * 4 + cb) * 4);
            #pragma unroll
            for (int r = 0; r < CLUSTER; r++) {
                unsigned rem;
                asm("mapa.shared::cluster.u32 %0, %1, %2;" : "=r"(rem) : "r"(dst), "r"(r));
                asm volatile("st.shared::cluster.f32 [%0], %1;" :: "r"(rem), "f"(h) : "memory");
            }
        }

        asm volatile("barrier.cluster.arrive.aligned;" ::: "memory");
        asm volatile("barrier.cluster.wait.aligned;" ::: "memory");
    }
}

// ============================ launch ============================
extern "C" void kernel_launch(void* const* d_in, const int* in_sizes, int n_in,
                              void* d_out, int out_size)
{
    const float* X  = (const float*)d_in[0];
    const float* Wf = (const float*)d_in[1];
    const float* bf = (const float*)d_in[2];
    const float* Wi = (const float*)d_in[3];
    const float* bi = (const float*)d_in[4];
    const float* Wg = (const float*)d_in[5];
    const float* bg = (const float*)d_in[6];
    const float* Wo = (const float*)d_in[7];
    const float* bo = (const float*)d_in[8];
    float* out = (float*)d_out;

    packB_kernel<<<(DIN * NC + 255) / 256, 256>>>(Wf, bf, Wi, bi, Wg, bg, Wo, bo);
    packA_kernel<<<(M_TOTAL * (DIN / 4) + 255) / 256, 256>>>(X);

    dim3 ggrid(NC / 128, M_TOTAL / 128);
    xproj_mma<<<ggrid, XT>>>();

    recur_kernel<<<NCTA, RTHR>>>(out, out_size);
}

// round 8
// speedup vs baseline: 1.2270x; 1.0370x over previous
#include <cuda_runtime.h>
#include <cuda_bf16.h>
#include <cstddef>
#include <cstdint>

#define TSTEPS 1024
#define BATCH  64
#define DIN    256
#define DHID   256
#define NC     1024
#define M_TOTAL (TSTEPS * BATCH)
#define KTOT   768            // split-bf16 virtual K: [Xhi|Xhi|Xlo] x [Whi;Wlo;Whi]

#define CLUSTER 8
#define NCTA    128
#define RTHR    1024          // 32 warps: kc(8) x c(128)

// packed column: pc = part*128 + u*4 + gate, j = part*32 + u, gate in {f,i,g,o}

__device__ float         g_xp[(size_t)M_TOTAL * NC];     // x-proj + bias [m][pc]
__device__ __nv_bfloat16 g_Ax[(size_t)M_TOTAL * KTOT];   // split-bf16 A' [m][k']
__device__ __nv_bfloat16 g_Bx[(size_t)NC * KTOT];        // split-bf16 B' [pc][k']
__device__ float         g_Whp[DHID * NC];               // fp32 Wh [part][kc8][i32][c128]
__device__ float         g_bp[NC];

// ============================ helpers ============================
__device__ __forceinline__ uint32_t smem_u32(const void* p) {
    uint32_t a;
    asm("{ .reg .u64 t; cvta.to.shared.u64 t, %1; cvt.u32.u64 %0, t; }" : "=r"(a) : "l"(p));
    return a;
}
#define SW128(off) ((off) ^ (((off) >> 3) & 0x70))

__device__ __forceinline__ void ldsm4(uint32_t* r, uint32_t addr) {
    asm volatile("ldmatrix.sync.aligned.m8n8.x4.shared.b16 {%0,%1,%2,%3}, [%4];"
                 : "=r"(r[0]), "=r"(r[1]), "=r"(r[2]), "=r"(r[3]) : "r"(addr));
}
__device__ __forceinline__ void mma16816(float* c, const uint32_t* a, uint32_t b0, uint32_t b1) {
    asm volatile("mma.sync.aligned.m16n8k16.row.col.f32.bf16.bf16.f32 "
                 "{%0,%1,%2,%3}, {%4,%5,%6,%7}, {%8,%9}, {%0,%1,%2,%3};"
                 : "+f"(c[0]), "+f"(c[1]), "+f"(c[2]), "+f"(c[3])
                 : "r"(a[0]), "r"(a[1]), "r"(a[2]), "r"(a[3]), "r"(b0), "r"(b1));
}

// ============================ pack kernels ============================
__global__ void packB_kernel(const float* __restrict__ Wf, const float* __restrict__ bf,
                             const float* __restrict__ Wi, const float* __restrict__ bi,
                             const float* __restrict__ Wg, const float* __restrict__ bg,
                             const float* __restrict__ Wo, const float* __restrict__ bo)
{
    int idx = blockIdx.x * blockDim.x + threadIdx.x;
    if (idx >= DIN * NC) return;
    int k    = idx >> 10;
    int pc   = idx & (NC - 1);
    int part = pc >> 7;
    int c    = pc & 127;
    int u    = c >> 2;
    int gate = c & 3;
    int j    = part * 32 + u;
    const float* W = (gate == 0) ? Wf : (gate == 1) ? Wi : (gate == 2) ? Wg : Wo;
    const float* b = (gate == 0) ? bf : (gate == 1) ? bi : (gate == 2) ? bg : bo;

    float wx = W[(size_t)k * DHID + j];
    __nv_bfloat16 hi = __float2bfloat16_rn(wx);
    float lo = wx - __bfloat162float(hi);
    g_Bx[(size_t)pc * KTOT + k]       = hi;                        // pairs with Xhi
    g_Bx[(size_t)pc * KTOT + 256 + k] = __float2bfloat16_rn(lo);   // pairs with Xhi
    g_Bx[(size_t)pc * KTOT + 512 + k] = hi;                        // pairs with Xlo

    float wh = W[(size_t)(DIN + k) * DHID + j];
    int kc = k >> 5, i = k & 31;   // 8 chunks of 32 k
    g_Whp[(size_t)(((part * 8 + kc) * 32) + i) * 128 + c] = wh;
    if (k == 0) g_bp[pc] = b[j];
}

__global__ void packA_kernel(const float* __restrict__ X)
{
    int idx = blockIdx.x * blockDim.x + threadIdx.x;
    if (idx >= M_TOTAL * (DIN / 4)) return;
    int m  = idx >> 6;
    int kq = idx & 63;
    float4 v = *(const float4*)&X[(size_t)m * DIN + kq * 4];
    __nv_bfloat162 h0 = __floats2bfloat162_rn(v.x, v.y);
    __nv_bfloat162 h1 = __floats2bfloat162_rn(v.z, v.w);
    float lx = v.x - __bfloat162float(h0.x);
    float ly = v.y - __bfloat162float(h0.y);
    float lz = v.z - __bfloat162float(h1.x);
    float lw = v.w - __bfloat162float(h1.y);
    __nv_bfloat162 l0 = __floats2bfloat162_rn(lx, ly);
    __nv_bfloat162 l1 = __floats2bfloat162_rn(lz, lw);
    size_t base = (size_t)m * KTOT + kq * 4;
    *(__nv_bfloat162*)&g_Ax[base]       = h0;
    *(__nv_bfloat162*)&g_Ax[base + 2]   = h1;
    *(__nv_bfloat162*)&g_Ax[base + 256] = h0;
    *(__nv_bfloat162*)&g_Ax[base + 258] = h1;
    *(__nv_bfloat162*)&g_Ax[base + 512] = l0;
    *(__nv_bfloat162*)&g_Ax[base + 514] = l1;
}

// ============================ xproj GEMM: mma.sync bf16 (R7, proven) ============================
#define XT 256
#define BK 64
#define NCHUNK (KTOT / BK)

__global__ __launch_bounds__(XT) void xproj_mma()
{
    __shared__ __align__(128) __nv_bfloat16 sAbuf[128 * 64];
    __shared__ __align__(128) __nv_bfloat16 sBbuf[128 * 64];

    const int tid    = threadIdx.x;
    const int wid    = tid >> 5;
    const int lane   = tid & 31;
    const int warp_m = wid >> 2;
    const int warp_n = wid & 3;
    const int n0     = blockIdx.x * 128;
    const int m0     = blockIdx.y * 128;

    const uint32_t sA32 = smem_u32(sAbuf);
    const uint32_t sB32 = smem_u32(sBbuf);
    char* sAp = (char*)sAbuf;
    char* sBp = (char*)sBbuf;

    const int g  = lane >> 3;
    const int lr = lane & 7;
    const int rA   = warp_m * 64 + (g & 1) * 8 + lr;
    const int hbA  = (g >> 1) * 16;
    const int rB   = warp_n * 32 + (g >> 1) * 8 + lr;
    const int hbB  = (g & 1) * 16;

    float acc[4][4][4];
    #pragma unroll
    for (int i = 0; i < 4; i++)
        #pragma unroll
        for (int jj = 0; jj < 4; jj++)
            #pragma unroll
            for (int q = 0; q < 4; q++) acc[i][jj][q] = 0.0f;

    uint4 rAv[4], rBv[4];
    #pragma unroll
    for (int i = 0; i < 4; i++) {
        int idx = tid + i * 256, row = idx >> 3, q = idx & 7;
        rAv[i] = *(const uint4*)&g_Ax[(size_t)(m0 + row) * KTOT + q * 8];
        rBv[i] = *(const uint4*)&g_Bx[(size_t)(n0 + row) * KTOT + q * 8];
    }

    for (int c = 0; c < NCHUNK; c++) {
        #pragma unroll
        for (int i = 0; i < 4; i++) {
            int idx = tid + i * 256, row = idx >> 3, q = idx & 7;
            *(uint4*)(sAp + SW128(row * 128 + q * 16)) = rAv[i];
            *(uint4*)(sBp + SW128(row * 128 + q * 16)) = rBv[i];
        }
        __syncthreads();

        if (c + 1 < NCHUNK) {
            #pragma unroll
            for (int i = 0; i < 4; i++) {
                int idx = tid + i * 256, row = idx >> 3, q = idx & 7;
                rAv[i] = *(const uint4*)&g_Ax[(size_t)(m0 + row) * KTOT + (c + 1) * BK + q * 8];
                rBv[i] = *(const uint4*)&g_Bx[(size_t)(n0 + row) * KTOT + (c + 1) * BK + q * 8];
            }
        }

        #pragma unroll
        for (int kk = 0; kk < 4; kk++) {
            uint32_t a[4][4], b[2][4];
            #pragma unroll
            for (int mt = 0; mt < 4; mt++) {
                int row = rA + mt * 16;
                ldsm4(a[mt], sA32 + row * 128 + ((kk * 32 + hbA) ^ ((row << 4) & 0x70)));
            }
            #pragma unroll
            for (int h = 0; h < 2; h++) {
                int row = rB + h * 16;
                ldsm4(b[h], sB32 + row * 128 + ((kk * 32 + hbB) ^ ((row << 4) & 0x70)));
            }
            #pragma unroll
            for (int mt = 0; mt < 4; mt++)
                #pragma unroll
                for (int nt = 0; nt < 4; nt++)
                    mma16816(acc[mt][nt], a[mt], b[nt >> 1][(nt & 1) * 2], b[nt >> 1][(nt & 1) * 2 + 1]);
        }
        __syncthreads();
    }

    const int er = lane >> 2;
    const int ec = (lane & 3) * 2;
    #pragma unroll
    for (int mt = 0; mt < 4; mt++) {
        int m = m0 + warp_m * 64 + mt * 16 + er;
        #pragma unroll
        for (int nt = 0; nt < 4; nt++) {
            int n = n0 + warp_n * 32 + nt * 8 + ec;
            float2 bias = *(const float2*)&g_bp[n];
            float2 o0 = make_float2(acc[mt][nt][0] + bias.x, acc[mt][nt][1] + bias.y);
            float2 o1 = make_float2(acc[mt][nt][2] + bias.x, acc[mt][nt][3] + bias.y);
            *(float2*)&g_xp[(size_t)m * NC + n]       = o0;
            *(float2*)&g_xp[(size_t)(m + 8) * NC + n] = o1;
        }
    }
}

// ============================ recurrent kernel: 1024 threads, no spills ============================
// 16 clusters of 8 CTAs; CTA rank = part. Thread (kc 0..7, c 0..127): 32-k chunk of the
// 4-batch dot for packed column c. w[32] in registers -> ~60 regs/thread at 1024 thr.
__global__ void __cluster_dims__(CLUSTER, 1, 1) __launch_bounds__(RTHR, 1)
recur_kernel(float* __restrict__ out)
{
    __shared__ __align__(16) float hbuf[2][DHID * 4];   // [buf][k*4 + b]  8 KB
    __shared__ __align__(16) float pbuf[8][4][128];     // [kc][b][c]     16 KB

    const int tid  = threadIdx.x;
    const int part = blockIdx.x & (CLUSTER - 1);
    const int grp  = blockIdx.x >> 3;
    const int kc   = tid >> 7;        // 0..7
    const int c    = tid & 127;       // 0..127

    float w[32];
    {
        const float* src = &g_Whp[(size_t)((part * 8 + kc) * 32) * 128 + c];
        #pragma unroll
        for (int i = 0; i < 32; i++) w[i] = src[(size_t)i * 128];
    }

    for (int i = tid; i < 2 * DHID * 4; i += RTHR) ((float*)hbuf)[i] = 0.0f;

    // combine identity (threads 0..127)
    const int cb = tid >> 5;
    const int cu = tid & 31;
    const int bg = grp * 4 + cb;
    const int j  = part * 32 + cu;
    float cstate = 0.0f;
    float hlast  = 0.0f;

    unsigned hbuf_base;
    asm("{ .reg .u64 t; cvta.to.shared.u64 t, %1; cvt.u32.u64 %0, t; }"
        : "=r"(hbuf_base) : "l"((void*)hbuf));

    __syncthreads();

    for (int t = 0; t < TSTEPS; t++) {
        const int p = t & 1;

        // prefetch this step's x-projection (threads 0..127, 16B each; hidden under dot)
        float4 xp4;
        if (tid < 128)
            xp4 = *(const float4*)&g_xp[((size_t)t * BATCH + bg) * NC + part * 128 + cu * 4];

        // ---- stage 1: 32-k partial dot for 4 batches via fma.rn.f32x2 ----
        {
            unsigned long long acc01 = 0ull, acc23 = 0ull;
            const float* hrow = &hbuf[p][kc * 128];
            #pragma unroll
            for (int i = 0; i < 32; i++) {
                ulonglong2 hh = *(const ulonglong2*)&hrow[i * 4];
                unsigned long long ww;
                asm("mov.b64 %0, {%1, %1};" : "=l"(ww) : "f"(w[i]));
                asm("fma.rn.f32x2 %0, %1, %2, %0;" : "+l"(acc01) : "l"(ww), "l"(hh.x));
                asm("fma.rn.f32x2 %0, %1, %2, %0;" : "+l"(acc23) : "l"(ww), "l"(hh.y));
            }
            float a0, a1, a2, a3;
            asm("mov.b64 {%0, %1}, %2;" : "=f"(a0), "=f"(a1) : "l"(acc01));
            asm("mov.b64 {%0, %1}, %2;" : "=f"(a2), "=f"(a3) : "l"(acc23));
            pbuf[kc][0][c] = a0;
            pbuf[kc][1][c] = a1;
            pbuf[kc][2][c] = a2;
            pbuf[kc][3][c] = a3;
        }
        __syncthreads();

        // ---- stage 2: combine + outputs + DSMEM broadcast (threads 0..127) ----
        if (tid < 128) {
            float4 s = make_float4(0.f, 0.f, 0.f, 0.f);
            #pragma unroll
            for (int q = 0; q < 8; q++) {
                float4 p4 = *(const float4*)&pbuf[q][cb][cu * 4];
                s.x += p4.x; s.y += p4.y; s.z += p4.z; s.w += p4.w;
            }
            float fv = s.x + xp4.x;
            float iv = s.y + xp4.y;
            float gv = s.z + xp4.z;
            float ov = s.w + xp4.w;
            float tf, ti, to, gt, ht;
            asm("tanh.approx.f32 %0, %1;" : "=f"(tf) : "f"(0.5f * fv));
            asm("tanh.approx.f32 %0, %1;" : "=f"(ti) : "f"(0.5f * iv));
            asm("tanh.approx.f32 %0, %1;" : "=f"(to) : "f"(0.5f * ov));
            asm("tanh.approx.f32 %0, %1;" : "=f"(gt) : "f"(gv));
            fv = 0.5f * tf + 0.5f;
            iv = 0.5f * ti + 0.5f;
            ov = 0.5f * to + 0.5f;
            cstate = fv * cstate + iv * gt;
            asm("tanh.approx.f32 %0, %1;" : "=f"(ht) : "f"(cstate));
            float h = ov * ht;
            hlast = h;

            out[(size_t)t * (BATCH * DHID) + (size_t)bg * DHID + j] = h;

            unsigned dst = hbuf_base + (unsigned)(((1 - p) * DHID * 4 + j * 4 + cb) * 4);
            #pragma unroll
            for (int r = 0; r < CLUSTER; r++) {
                unsigned rem;
                asm("mapa.shared::cluster.u32 %0, %1, %2;" : "=r"(rem) : "r"(dst), "r"(r));
                asm volatile("st.shared::cluster.f32 [%0], %1;" :: "r"(rem), "f"(h) : "memory");
            }
        }

        asm volatile("barrier.cluster.arrive.aligned;" ::: "memory");
        asm volatile("barrier.cluster.wait.aligned;" ::: "memory");
    }

    // final hT / cT
    if (tid < 128) {
        const size_t HT_OFF = (size_t)TSTEPS * BATCH * DHID;
        out[HT_OFF + (size_t)bg * DHID + j] = hlast;
        out[HT_OFF + (size_t)BATCH * DHID + (size_t)bg * DHID + j] = cstate;
    }
}

// ============================ launch ============================
extern "C" void kernel_launch(void* const* d_in, const int* in_sizes, int n_in,
                              void* d_out, int out_size)
{
    const float* X  = (const float*)d_in[0];
    const float* Wf = (const float*)d_in[1];
    const float* bf = (const float*)d_in[2];
    const float* Wi = (const float*)d_in[3];
    const float* bi = (const float*)d_in[4];
    const float* Wg = (const float*)d_in[5];
    const float* bg = (const float*)d_in[6];
    const float* Wo = (const float*)d_in[7];
    const float* bo = (const float*)d_in[8];
    float* out = (float*)d_out;

    packB_kernel<<<(DIN * NC + 255) / 256, 256>>>(Wf, bf, Wi, bi, Wg, bg, Wo, bo);
    packA_kernel<<<(M_TOTAL * (DIN / 4) + 255) / 256, 256>>>(X);

    dim3 ggrid(NC / 128, M_TOTAL / 128);
    xproj_mma<<<ggrid, XT>>>();

    recur_kernel<<<NCTA, RTHR>>>(out);
}